// round 16
// baseline (speedup 1.0000x reference)
#include <cuda_runtime.h>
#include <cuda_bf16.h>
#include <math.h>

// Problem dims (fixed for this instance)
#define NN   2048
#define BB   8
#define KK   4
#define NBK  (BB*KK)      // 32
#define NT   512          // fused row kernel block size
#define CG_REG 1e-6f
#define TWOPI_D 6.283185307179586

// ---------------- scratch (device globals; no allocations allowed) ----------------
__device__ float g_cx[NBK*NN];
__device__ float g_cy[NBK*NN];
__device__ float g_u[BB*NN];
__device__ unsigned g_tick[BB];   // per-batch arrival counter (wraps mod 4 per call)

// ---------------- helpers ----------------
// Warp all-reduce: 5-level shfl butterfly (redux.sync.add.f32 NOT supported on sm_103).
__device__ __forceinline__ float warpRedux(float v) {
    #pragma unroll
    for (int o = 16; o > 0; o >>= 1) v += __shfl_xor_sync(0xffffffffu, v, o);
    return v;
}

// Sum NW floats (NW multiple of 4) from 16B-aligned smem via float4 loads.
template<int NW>
__device__ __forceinline__ float sumP(const float* s) {
    float acc = 0.f;
    #pragma unroll
    for (int k = 0; k < NW/4; k++) {
        float4 v = reinterpret_cast<const float4*>(s)[k];
        acc += (v.x + v.y) + (v.z + v.w);
    }
    return acc;
}

template<int BARID, int NTHR>
__device__ __forceinline__ void barx() {
    asm volatile("bar.sync %0, %1;" :: "n"(BARID), "n"(NTHR) : "memory");
}

// Pentadiagonal opedoub apply on register-resident v (EPT consecutive elems per
// thread). Neighbors via intra-warp shfl; warp-edge values supplied in hl/hr.
template<int EPT>
__device__ __forceinline__ void stencil_apply(const float p[EPT],
    float hl0, float hl1, float hr0, float hr1,
    bool lane0, bool lane31, bool firstT, bool lastT, float st[EPT])
{
    float lm2 = __shfl_up_sync(0xffffffffu, p[EPT-2], 1);
    float lm1 = __shfl_up_sync(0xffffffffu, p[EPT-1], 1);
    float rp0 = __shfl_down_sync(0xffffffffu, p[0], 1);
    float rp1 = __shfl_down_sync(0xffffffffu, p[1], 1);
    if (lane0)  { lm2 = hl0; lm1 = hl1; }
    if (lane31) { rp0 = hr0; rp1 = hr1; }
    float wb[EPT+4];
    wb[0] = lm2; wb[1] = lm1;
    #pragma unroll
    for (int j = 0; j < EPT; j++) wb[2+j] = p[j];
    wb[EPT+2] = rp0; wb[EPT+3] = rp1;
    #pragma unroll
    for (int j = 0; j < EPT; j++)
        st[j] = wb[j] - 4.0f*wb[j+1] + 6.0f*wb[j+2] - 4.0f*wb[j+3] + wb[j+4];
    if (firstT) {
        st[0] =  2.0f*p[0] - 3.0f*p[1] + p[2];
        st[1] = -3.0f*p[0] + 6.0f*p[1] - 4.0f*p[2] + p[3];
    }
    if (lastT) {
        st[EPT-2] = p[EPT-4] - 4.0f*p[EPT-3] + 6.0f*p[EPT-2] - 3.0f*p[EPT-1];
        st[EPT-1] = p[EPT-3] - 3.0f*p[EPT-2] + 2.0f*p[EPT-1];
    }
}

// Pipelined (Chronopoulos-Gear) register-resident CG: ONE barrier/iteration.
// Solves (coef*opedoub + diag(dreg)) x = rhs over NW warps, EPT consecutive
// elems/thread (EPT<=8: register ceiling, EPT=16 spills -- R11).
// Per iter: s = A r; reduce (gam = r.r, del = r.s) in ONE barrier; then
//   bta = gam/gam_old            (== reference rsnew/rsold)
//   pAp = del - bta*gam/alp_old  (exact identity to p.Ap; ~1-bit cancellation,
//                                 NOT the R8 catastrophic expansion)
//   a   = gam/(pAp + 1e-12)
//   p = r + bta*p; Ap = s + bta*Ap; x += a*p; r -= a*Ap.
// Stencil runs on r; r warp-edge halos maintained by recurrence from published
// s-edges. Slots parity double-buffered (>=1 barrier between write and prior
// reads -> race-free). gam_k == reference rsnew_{k-1}, so the freeze check
// here reproduces the reference's done flow exactly.
template<int EPT, int NW, int BARID, bool X0Z>
__device__ void cg_pipe(int lt, float coef, const float dreg[EPT],
                        const float rhs[EPT], const float x0[EPT], float xout[EPT],
                        float2* sred /*[2*NW]*/, float (*eLo)[2], float (*eHi)[2] /*[2*NW][2]*/)
{
    constexpr int NTHR = NW*32;
    const int lane = lt & 31, w = lt >> 5;
    const bool l0 = (lane == 0), l31 = (lane == 31);
    const bool fT = (lt == 0), lT = (lt == NTHR-1);
    float r[EPT], p[EPT], Ap[EPT], x[EPT];
    float rhl0=0.f, rhl1=0.f, rhr0=0.f, rhr1=0.f;   // neighbor r-edge halos
    float Ahl0=0.f, Ahl1=0.f, Ahr0=0.f, Ahr1=0.f;   // neighbor Ap-edge halos
    int pb = 0;

    if (X0Z) {
        #pragma unroll
        for (int j = 0; j < EPT; j++) { r[j] = rhs[j]; x[j] = 0.f; p[j] = 0.f; Ap[j] = 0.f; }
        if (l0)  { eLo[pb*NW+w][0] = r[0];     eLo[pb*NW+w][1] = r[1]; }
        if (l31) { eHi[pb*NW+w][0] = r[EPT-2]; eHi[pb*NW+w][1] = r[EPT-1]; }
        barx<BARID, NTHR>();
        if (l0  && w > 0)    { rhl0 = eHi[pb*NW+w-1][0]; rhl1 = eHi[pb*NW+w-1][1]; }
        if (l31 && w < NW-1) { rhr0 = eLo[pb*NW+w+1][0]; rhr1 = eLo[pb*NW+w+1][1]; }
        pb ^= 1;
    } else {
        #pragma unroll
        for (int j = 0; j < EPT; j++) { x[j] = x0[j]; p[j] = 0.f; Ap[j] = 0.f; }
        if (l0)  { eLo[pb*NW+w][0] = x0[0];     eLo[pb*NW+w][1] = x0[1]; }
        if (l31) { eHi[pb*NW+w][0] = x0[EPT-2]; eHi[pb*NW+w][1] = x0[EPT-1]; }
        barx<BARID, NTHR>();
        float xl0=0.f, xl1=0.f, xr0=0.f, xr1=0.f;
        if (l0  && w > 0)    { xl0 = eHi[pb*NW+w-1][0]; xl1 = eHi[pb*NW+w-1][1]; }
        if (l31 && w < NW-1) { xr0 = eLo[pb*NW+w+1][0]; xr1 = eLo[pb*NW+w+1][1]; }
        pb ^= 1;
        float st[EPT];
        stencil_apply<EPT>(x, xl0, xl1, xr0, xr1, l0, l31, fT, lT, st);
        #pragma unroll
        for (int j = 0; j < EPT; j++) r[j] = rhs[j] - (coef*st[j] + dreg[j]*x[j]);
        if (l0)  { eLo[pb*NW+w][0] = r[0];     eLo[pb*NW+w][1] = r[1]; }
        if (l31) { eHi[pb*NW+w][0] = r[EPT-2]; eHi[pb*NW+w][1] = r[EPT-1]; }
        barx<BARID, NTHR>();
        if (l0  && w > 0)    { rhl0 = eHi[pb*NW+w-1][0]; rhl1 = eHi[pb*NW+w-1][1]; }
        if (l31 && w < NW-1) { rhr0 = eLo[pb*NW+w+1][0]; rhr1 = eLo[pb*NW+w+1][1]; }
        pb ^= 1;
    }

    float gam_old = 1.f, alp_old = 1.f;
    bool done = false;
    for (int it = 0; it < 30; it++) {
        float st[EPT], sv[EPT];
        stencil_apply<EPT>(r, rhl0, rhl1, rhr0, rhr1, l0, l31, fT, lT, st);
        float g0=0.f, g1=0.f, d0=0.f, d1=0.f;
        #pragma unroll
        for (int j = 0; j < EPT; j++) {
            sv[j] = coef*st[j] + dreg[j]*r[j];
            if (j & 1) { g1 += r[j]*r[j]; d1 += r[j]*sv[j]; }
            else       { g0 += r[j]*r[j]; d0 += r[j]*sv[j]; }
        }
        float g = g0 + g1, d = d0 + d1;
        #pragma unroll
        for (int o = 16; o > 0; o >>= 1) {
            g += __shfl_xor_sync(0xffffffffu, g, o);
            d += __shfl_xor_sync(0xffffffffu, d, o);
        }
        if (l0) {
            sred[pb*NW+w] = make_float2(g, d);
            eLo[pb*NW+w][0] = sv[0]; eLo[pb*NW+w][1] = sv[1];
        }
        if (l31) { eHi[pb*NW+w][0] = sv[EPT-2]; eHi[pb*NW+w][1] = sv[EPT-1]; }
        barx<BARID, NTHR>();
        float gam = 0.f, del = 0.f;
        #pragma unroll
        for (int k = 0; k < NW/2; k++) {
            float4 v = reinterpret_cast<const float4*>(sred + pb*NW)[k];
            gam += v.x + v.z;
            del += v.y + v.w;
        }
        done = done || (gam < 1e-12f);   // gam == reference rsnew of prev iter
        float bta = (it == 0) ? 0.f : __fdividef(gam, gam_old + 1e-12f);
        float pAp = del - bta * __fdividef(gam, alp_old);
        float a = __fdividef(gam, pAp + 1e-12f);
        if (!done) {
            #pragma unroll
            for (int j = 0; j < EPT; j++) {
                p[j]  = r[j]  + bta*p[j];
                Ap[j] = sv[j] + bta*Ap[j];
                x[j] += a*p[j];
                r[j] -= a*Ap[j];
            }
            if (l0 && w > 0) {
                float sL0 = eHi[pb*NW+w-1][0], sL1 = eHi[pb*NW+w-1][1];
                Ahl0 = sL0 + bta*Ahl0; Ahl1 = sL1 + bta*Ahl1;
                rhl0 -= a*Ahl0; rhl1 -= a*Ahl1;
            }
            if (l31 && w < NW-1) {
                float sR0 = eLo[pb*NW+w+1][0], sR1 = eLo[pb*NW+w+1][1];
                Ahr0 = sR0 + bta*Ahr0; Ahr1 = sR1 + bta*Ahr1;
                rhr0 -= a*Ahr0; rhr1 -= a*Ahr1;
            }
            gam_old = gam; alp_old = a;
        }
        pb ^= 1;
    }
    #pragma unroll
    for (int j = 0; j < EPT; j++) xout[j] = x[j];
}

// cumulative trapezoid over NN with NTHR threads (NN/NTHR consecutive elems
// per thread), double accum, named barrier BARID (group-local).
template<int NTHR, int BARID>
__device__ void cumtz(int lt, const float* y, float dxf, double* warpoff, double* Pout) {
    constexpr int EPT2 = NN/NTHR, NW = NTHR/32;
    int lane = lt & 31, w = lt >> 5, base = lt*EPT2;
    double acc = 0.0, pre[EPT2];
    #pragma unroll
    for (int m = 0; m < EPT2; m++) {
        int j = base + m;
        float a = (j < NN-1) ? ((y[j] + y[j+1]) * (0.5f*dxf)) : 0.0f;
        pre[m] = acc; acc += (double)a;
    }
    double v = acc;
    #pragma unroll
    for (int o = 1; o < 32; o <<= 1) {
        double n = __shfl_up_sync(0xffffffffu, v, o);
        if (lane >= o) v += n;
    }
    if (lane == 31) warpoff[w] = v;
    double excl = v - acc;
    barx<BARID, NTHR>();
    if (lt == 0) {
        double run = 0.0;
        #pragma unroll
        for (int ww = 0; ww < NW; ww++) { double tmp = warpoff[ww]; warpoff[ww] = run; run += tmp; }
    }
    barx<BARID, NTHR>();
    double off = warpoff[w] + excl;
    #pragma unroll
    for (int m = 0; m < EPT2; m++) Pout[m] = off + pre[m];
}

// ---------------- K1: fully fused per-row pipeline ----------------
// 32 blocks x 512 threads.
// warps 0-7:  phase cumtrapz(eIF) -> cos/sin (named bar 3)
// warps 8-15: hyperparameter MLP (identical in every block; named bar 4)
// then: u projection -> concurrent x/y pipelined CG (256 thr each, bars 1/2)
// -> smooth pipelined CG (512 thr, bar 0) -> epilogue -> last CTA per batch
// does bsx/bsy/lamuda (ticket via g_tick).
__global__ void __launch_bounds__(NT) row_kernel(
    const float* s, const float* eIF, const float* xm, const float* ym,
    const float* sum_x, const float* sum_y, const float* lamuda,
    const int* mode_mask, const float* fs_p, const float* var_p,
    const float* init_freqs, const float* alpha_p, const float* beta_p,
    const float* fe_w1, const float* fe_b1, const float* fe_w2, const float* fe_b2,
    const float* pr_w1, const float* pr_b1, const float* pr_w2, const float* pr_b2,
    const float* pr_w3, const float* pr_b3, const float* iter_w, const int* iter_p,
    float* out_eIF, float* out_xm, float* out_ym,
    float* out_bsx, float* out_bsy, float* out_lam, float* out_scal)
{
    __shared__ float bufA[NN];   // cos  -> xs solution
    __shared__ float bufB[NN];   // sin  -> ys solution
    __shared__ float bufC[NN];   // MLP scratch -> new_eIF staging
    __shared__ double warpoff[16];
    __shared__ __align__(16) float2 sredX[16], sredY[16], sredS[32];
    __shared__ __align__(16) float sredF[16];
    __shared__ float eXLo[16][2], eXHi[16][2];
    __shared__ float eYLo[16][2], eYHi[16][2];
    __shared__ float eSLo[32][2], eSHi[32][2];
    __shared__ float sAB[4];     // [na, nb, betathr, bt]
    __shared__ int   isLast;

    const int row = blockIdx.x, t = threadIdx.x;
    const int b = row / KK, ro = row*NN, bo = b*NN;
    const float dxf = 1.0f / (*fs_p);

    if (t < 256) {
        // ---- phase half (warps 0-7) ----
        double P[8];
        cumtz<256, 3>(t, eIF + ro, dxf, warpoff, P);
        int base = t*8;
        #pragma unroll
        for (int m = 0; m < 8; m++) {
            double frac = P[m] - floor(P[m]);
            float ph = (float)(frac * TWOPI_D);
            float sn, cs;
            __sincosf(ph, &sn, &cs);
            bufA[base+m] = cs;
            bufB[base+m] = sn;
        }
    } else {
        // ---- MLP half (warps 8-15, lt in 0..255) ----
        int lt = t - 256;
        float* m_avg = bufC;          // 8
        float* m_h1  = bufC + 8;      // 256  [b*32+j]
        float* m_h2  = bufC + 264;    // 144  [b*18+j]
        float* m_z1  = bufC + 408;    // 512  [b*64+j]
        float* m_z2  = bufC + 920;    // 256  [b*32+j]
        float* m_res = bufC + 1176;   // 16   [b*2+j]
        float alpha = *alpha_p, beta = *beta_p;
        if (lt == 0) {
            int it = *iter_p;
            sAB[3] = (float)pow(10.0, (double)it/36.0 - 10.0);
        }
        if (lt < BB) {
            float a = 0.f;
            #pragma unroll
            for (int k = 0; k < KK; k++) a += init_freqs[lt*KK + k];
            m_avg[lt] = a / (float)KK;
        }
        barx<4, 256>();
        {   // fe1: 8x32
            int bb2 = lt >> 5, j = lt & 31;
            float v = fe_w1[j]*m_avg[bb2] + fe_b1[j];
            m_h1[bb2*32 + j] = v > 0.f ? v : 0.f;
        }
        barx<4, 256>();
        if (lt < BB*16) { // fe2: 8x16
            int bb2 = lt >> 4, j = lt & 15;
            float acc = fe_b2[j];
            #pragma unroll
            for (int k = 0; k < 32; k++) acc += fe_w2[j*32 + k]*m_h1[bb2*32 + k];
            m_h2[bb2*18 + j] = acc > 0.f ? acc : 0.f;
        } else if (lt < BB*16 + BB) {
            int bb2 = lt - BB*16;
            m_h2[bb2*18 + 16] = alpha;
            m_h2[bb2*18 + 17] = beta;
        }
        barx<4, 256>();
        for (int idx = lt; idx < BB*64; idx += 256) { // pr1: 8x64
            int bb2 = idx >> 6, j = idx & 63;
            float acc = pr_b1[j];
            #pragma unroll
            for (int k = 0; k < 18; k++) acc += pr_w1[j*18 + k]*m_h2[bb2*18 + k];
            m_z1[bb2*64 + j] = acc > 0.f ? acc : 0.f;
        }
        barx<4, 256>();
        {   // pr2: 8x32
            int bb2 = lt >> 5, j = lt & 31;
            float acc = pr_b2[j];
            #pragma unroll
            for (int k = 0; k < 64; k++) acc += pr_w2[j*64 + k]*m_z1[bb2*64 + k];
            m_z2[bb2*32 + j] = acc > 0.f ? acc : 0.f;
        }
        barx<4, 256>();
        if (lt < BB*2) { // pr3 + tanh + scaling
            int bb2 = lt >> 1, j = lt & 1;
            float acc = pr_b3[j];
            #pragma unroll
            for (int k = 0; k < 32; k++) acc += pr_w3[j*32 + k]*m_z2[bb2*32 + k];
            float itf = (float)(*iter_p);
            float fac = 1.0f / (1.0f + expf(-(*iter_w)*itf));
            m_res[bb2*2 + j] = tanhf(acc) * fac * 0.1f;
        }
        barx<4, 256>();
        if (lt == 0) {
            float m0 = 0.f, m1 = 0.f;
            #pragma unroll
            for (int bb2 = 0; bb2 < BB; bb2++) { m0 += m_res[bb2*2]; m1 += m_res[bb2*2+1]; }
            m0 /= (float)BB; m1 /= (float)BB;
            float na = fminf(fmaxf(alpha + m0*alpha, 1e-6f), 0.01f);
            float nb = fminf(fmaxf(beta + m1*beta, 1e-6f), 0.1f);
            float bthr = fminf(sAB[3], nb);
            sAB[0] = na; sAB[1] = nb; sAB[2] = bthr;
            if (row == 0) { out_scal[0] = na; out_scal[1] = nb; }
        }
    }
    __syncthreads();

    const float na = sAB[0];
    const float bthr = sAB[2];

    // --- ||v|| for the norm-ball projection (u = scale*v) ---
    {
        float d0 = 0.f, d1 = 0.f;
        int b4 = t*4;
        #pragma unroll
        for (int m = 0; m < 4; m++) {
            int i = b4 + m;
            float v = s[bo+i] - sum_x[bo+i] - sum_y[bo+i] - lamuda[bo+i]/na;
            if (m & 1) d1 += v*v; else d0 += v*v;
        }
        float dd = warpRedux(d0 + d1);
        if ((t & 31) == 0) sredF[t >> 5] = dd;
    }
    __syncthreads();
    float n2 = sumP<16>(sredF);
    float nrm = sqrtf(n2);
    float e = sqrtf((float)NN * (*var_p));
    float scale = (nrm > e) ? (e / fmaxf(nrm, 1e-30f)) : 1.0f;

    // --- x/y CG setup (8 consecutive elems per thread within each half) ---
    const bool isY = (t >= 256);
    const int lt = t & 255;
    float dreg[8], rhs[8], x0v[8], sol[8];
    {
        int base = lt*8;
        #pragma unroll
        for (int j = 0; j < 8; j++) {
            int i = base + j;
            float c = bufA[i], sn = bufB[i];
            float xmv = xm[ro+i], ymv = ym[ro+i];
            float v = s[bo+i] - sum_x[bo+i] - sum_y[bo+i] - lamuda[bo+i]/na;
            float u = scale * v;
            float resid = v - u + xmv*c + ymv*sn;
            if (!isY) {
                dreg[j] = c*c + CG_REG;  rhs[j] = c*resid;  x0v[j] = xmv;
                g_u[bo+i] = u;   // x-half covers all i; dup across k-CTAs identical
            } else {
                dreg[j] = sn*sn + CG_REG; rhs[j] = sn*resid; x0v[j] = ymv;
            }
        }
    }
    __syncthreads();   // bufA/bufB reads done before solutions overwrite them
    float coef = 2.0f / na;
    if (!isY)
        cg_pipe<8,8,1,false>(lt, coef, dreg, rhs, x0v, sol, sredX, eXLo, eXHi);
    else
        cg_pipe<8,8,2,false>(lt, coef, dreg, rhs, x0v, sol, sredY, eYLo, eYHi);
    {
        int base = lt*8;
        float* dst = isY ? bufB : bufA;
        #pragma unroll
        for (int j = 0; j < 8; j++) dst[base+j] = sol[j];
    }
    __syncthreads();

    // --- smooth CG (full block, 4 consecutive elems per thread) ---
    float dregS[4], rhsS[4], zero4[4], solS[4];
    {
        int base = t*4;
        const float TWOPIF = 6.2831853071795864769f;
        #pragma unroll
        for (int m = 0; m < 4; m++) {
            int i = base + m;
            float xv = bufA[i], yv = bufB[i];
            float xb = (i == 0)    ? (bufA[1]-bufA[0]) / dxf
                     : (i == NN-1) ? (bufA[NN-1]-bufA[NN-2]) / dxf
                     : (bufA[i+1]-bufA[i-1]) / (2.0f*dxf);
            float yb = (i == 0)    ? (bufB[1]-bufB[0]) / dxf
                     : (i == NN-1) ? (bufB[NN-1]-bufB[NN-2]) / dxf
                     : (bufB[i+1]-bufB[i-1]) / (2.0f*dxf);
            float denom = xv*xv + yv*yv + 1e-12f;
            rhsS[m]  = (xv*yb - yv*xb) / (denom * TWOPIF);
            dregS[m] = 1.0f + CG_REG;
            zero4[m] = 0.f;
        }
    }
    float coefS = 2.0f / bthr;
    cg_pipe<4,16,0,true>(t, coefS, dregS, rhsS, zero4, solS, sredS, eSLo, eSHi);

    // --- epilogue: outputs + new-phase contributions ---
    bool active = (mode_mask[row] != 0);
    float maskf = active ? 1.0f : 0.0f;
    float nxm[4], nym[4];
    {
        int base = t*4;
        #pragma unroll
        for (int m = 0; m < 4; m++) {
            int i = base + m;
            float ne = active ? (eIF[ro+i] - 0.5f*solS[m]) : eIF[ro+i];
            out_eIF[ro+i] = ne;
            nxm[m] = active ? bufA[i] : xm[ro+i];
            nym[m] = active ? bufB[i] : ym[ro+i];
            out_xm[ro+i] = nxm[m];
            out_ym[ro+i] = nym[m];
            bufC[i] = ne;
        }
    }
    __syncthreads();
    double P2[4];
    cumtz<512, 0>(t, bufC, dxf, warpoff, P2);
    {
        int base = t*4;
        #pragma unroll
        for (int m = 0; m < 4; m++) {
            int i = base + m;
            double frac = P2[m] - floor(P2[m]);
            float ph = (float)(frac * TWOPI_D);
            float sn, cs;
            __sincosf(ph, &sn, &cs);
            g_cx[ro+i] = maskf * nxm[m] * cs;
            g_cy[ro+i] = maskf * nym[m] * sn;
        }
    }

    // --- merged final: last-arriving CTA of each batch computes bsx/bsy/lamuda ---
    __threadfence();
    __syncthreads();
    if (t == 0) {
        unsigned tk = atomicAdd(&g_tick[b], 1u);
        isLast = ((tk & 3u) == 3u) ? 1 : 0;
        __threadfence();   // acquire: order subsequent reads after the atomic
    }
    __syncthreads();
    if (isLast) {
        for (int i = t; i < NN; i += NT) {
            float bx = 0.f, by = 0.f;
            #pragma unroll
            for (int k = 0; k < KK; k++) {
                bx += g_cx[(b*KK + k)*NN + i];
                by += g_cy[(b*KK + k)*NN + i];
            }
            out_bsx[bo + i] = bx;
            out_bsy[bo + i] = by;
            out_lam[bo + i] = lamuda[bo + i] + na * (g_u[bo + i] + bx + by - s[bo + i]);
        }
    }
}

// ---------------- launch ----------------
extern "C" void kernel_launch(void* const* d_in, const int* in_sizes, int n_in,
                              void* d_out, int out_size) {
    const float* s          = (const float*)d_in[0];
    const float* eIF        = (const float*)d_in[1];
    const float* xm         = (const float*)d_in[2];
    const float* ym         = (const float*)d_in[3];
    const float* sum_x      = (const float*)d_in[4];
    const float* sum_y      = (const float*)d_in[5];
    const float* lamuda     = (const float*)d_in[6];
    const float* init_freqs = (const float*)d_in[7];
    const int*   mode_mask  = (const int*)d_in[8];
    const float* alpha      = (const float*)d_in[9];
    const float* beta       = (const float*)d_in[10];
    const float* var        = (const float*)d_in[11];
    const float* fs         = (const float*)d_in[12];
    const int*   iteration  = (const int*)d_in[13];
    const float* fe_w1      = (const float*)d_in[14];
    const float* fe_b1      = (const float*)d_in[15];
    const float* fe_w2      = (const float*)d_in[16];
    const float* fe_b2      = (const float*)d_in[17];
    const float* pr_w1      = (const float*)d_in[18];
    const float* pr_b1      = (const float*)d_in[19];
    const float* pr_w2      = (const float*)d_in[20];
    const float* pr_b2      = (const float*)d_in[21];
    const float* pr_w3      = (const float*)d_in[22];
    const float* pr_b3      = (const float*)d_in[23];
    const float* iter_w     = (const float*)d_in[24];

    float* out = (float*)d_out;
    const int BKN = NBK * NN;   // 65536
    const int BN  = BB * NN;    // 16384
    float* o_eIF  = out;
    float* o_xm   = out + BKN;
    float* o_ym   = out + 2*BKN;
    float* o_bsx  = out + 3*BKN;
    float* o_bsy  = o_bsx + BN;
    float* o_lam  = o_bsy + BN;
    float* o_scal = o_lam + BN;   // [new_alpha, new_beta]

    row_kernel<<<NBK, NT>>>(s, eIF, xm, ym, sum_x, sum_y, lamuda, mode_mask,
                            fs, var, init_freqs, alpha, beta,
                            fe_w1, fe_b1, fe_w2, fe_b2,
                            pr_w1, pr_b1, pr_w2, pr_b2, pr_w3, pr_b3,
                            iter_w, iteration,
                            o_eIF, o_xm, o_ym, o_bsx, o_bsy, o_lam, o_scal);
}